// round 11
// baseline (speedup 1.0000x reference)
#include <cuda_runtime.h>
#include <cstdint>
#include <math.h>

#define NN 100000
#define EE 640000
#define DDIM 128
#define HHID 256
#define LLAY 3
#define QDIM 768

// ---------------- device scratch (no allocations allowed) -------------------
__device__ float g_nodeA[(size_t)NN * DDIM];
__device__ float g_nodeB[(size_t)NN * DDIM];
__device__ float g_edgeA[(size_t)EE * DDIM];
__device__ float g_edgeB[(size_t)EE * DDIM];
__device__ float g_agg[(size_t)NN * DDIM];
__device__ float g_q[DDIM];
__device__ float g_qbias[HHID];
__device__ float g_eW1T[256 * 384];   // [N=256, K=384] tf32
__device__ float g_eW2T[128 * 256];   // [N=128, K=256] tf32
__device__ float g_nW1T[256 * 256];   // [N=256, K=256] tf32
__device__ float g_nW2T[128 * 256];   // [N=128, K=256] tf32

// ---------------- helpers ----------------------------------------------------
__device__ __forceinline__ uint32_t f2tf32(float f) {
    uint32_t u;
    asm("cvt.rna.tf32.f32 %0, %1;" : "=r"(u) : "f"(f));
    return u;
}
__device__ __forceinline__ float tf32f(float f) { return __uint_as_float(f2tf32(f)); }

__device__ __forceinline__ void mma8(float* d, const uint32_t* a, uint32_t b0, uint32_t b1) {
    asm volatile(
        "mma.sync.aligned.m16n8k8.row.col.f32.tf32.tf32.f32 "
        "{%0,%1,%2,%3}, {%4,%5,%6,%7}, {%8,%9}, {%0,%1,%2,%3};"
        : "+f"(d[0]), "+f"(d[1]), "+f"(d[2]), "+f"(d[3])
        : "r"(a[0]), "r"(a[1]), "r"(a[2]), "r"(a[3]), "r"(b0), "r"(b1));
}
__device__ __forceinline__ void red4(float* p, float4 v) {
    asm volatile("red.global.add.v4.f32 [%0], {%1, %2, %3, %4};"
                 :: "l"(p), "f"(v.x), "f"(v.y), "f"(v.z), "f"(v.w) : "memory");
}

// smem layout in float words
enum {
    HS_STRIDE = 260,                  // bank = (4g+t): conflict-free A-frag reads
    HS_OFF = 0,                       // 128 x 260           = 33280
    AS_OFF = 33280, AS_STRIDE = 36,   // 128 x 36            = 4608   (GEMM1 A)
    BS_OFF = 37888, BS_STRIDE = 36,   // 256 x 36            = 9216   (GEMM1 B)
    W2_OFF = 33280, W2_STRIDE = 132,  // 128 x 132           = 16896  (GEMM2 B, overlays As+Bs)
    QB_OFF = 50176,                   // 256
    B2B_OFF = 50432,                  // 128
    SS_OFF = 50560,                   // 128 (int)
    SD_OFF = 50688,                   // 128 (int)
    SM_WORDS = 50816
};
#define SMEM_BYTES (SM_WORDS * 4)     // 203264 < 232448 cap

// ---------------- small kernels ---------------------------------------------
__global__ void zero_kernel(float4* p, int n4) {
    int i = blockIdx.x * blockDim.x + threadIdx.x;
    if (i < n4) p[i] = make_float4(0.f, 0.f, 0.f, 0.f);
}
__global__ void q_proj_kernel(const float* __restrict__ qe, const float* __restrict__ qW,
                              const float* __restrict__ qb, float* __restrict__ qout) {
    int d = threadIdx.x;
    float s = qb[d];
    #pragma unroll 8
    for (int k = 0; k < QDIM; k++) s += qe[k] * qW[(size_t)k * DDIM + d];
    qout[d] = s;
}
__global__ void qbias_kernel(const float* __restrict__ q, const float* __restrict__ eW1l,
                             const float* __restrict__ eb1l, float* __restrict__ qbias) {
    int h = threadIdx.x;
    float s = eb1l[h];
    #pragma unroll 8
    for (int k = 0; k < DDIM; k++) s += q[k] * eW1l[(size_t)(384 + k) * HHID + h];
    qbias[h] = s;
}
// fused transpose of all 4 weight matrices for one layer (896 blocks x 256)
__global__ void transpose_all_kernel(
    const float* __restrict__ eW1, const float* __restrict__ eW2,
    const float* __restrict__ nW1, const float* __restrict__ nW2,
    float* __restrict__ eW1T, float* __restrict__ eW2T,
    float* __restrict__ nW1T, float* __restrict__ nW2T) {
    int b = blockIdx.x;
    const float* in; float* out; int K, base;
    if (b < 384)      { in = eW1; out = eW1T; K = 384; base = 0; }
    else if (b < 512) { in = eW2; out = eW2T; K = 256; base = 384; }
    else if (b < 768) { in = nW1; out = nW1T; K = 256; base = 512; }
    else              { in = nW2; out = nW2T; K = 256; base = 768; }
    int N = (b < 384 || (b >= 512 && b < 768)) ? 256 : 128;
    int i = (b - base) * 256 + threadIdx.x;
    int n = i / K, k = i - n * K;
    out[i] = tf32f(in[(size_t)k * N + n]);
}
__global__ void score_kernel(const float* __restrict__ h, const float* __restrict__ w,
                             const float* __restrict__ bptr, float* __restrict__ out, int count) {
    int gwarp = (blockIdx.x * blockDim.x + threadIdx.x) >> 5;
    int lane = threadIdx.x & 31;
    if (gwarp >= count) return;
    float4 a = ((const float4*)(h + (size_t)gwarp * DDIM))[lane];
    float4 wv = ((const float4*)w)[lane];
    float s = a.x * wv.x + a.y * wv.y + a.z * wv.z + a.w * wv.w;
    #pragma unroll
    for (int o = 16; o; o >>= 1) s += __shfl_xor_sync(0xffffffffu, s, o);
    if (lane == 0) out[gwarp] = 1.f / (1.f + expf(-(s + bptr[0])));
}

// ---------------- shared GEMM pieces -----------------------------------------
__device__ __forceinline__ void gemm1_chunk_mma(const float* As, const float* Bs,
                                                int mw, int nw, int g, int t,
                                                float d1[2][8][4]) {
    #pragma unroll
    for (int ks = 0; ks < 4; ks++) {
        int k = ks * 8;
        uint32_t a[2][4];
        #pragma unroll
        for (int mt = 0; mt < 2; mt++) {
            int r = mw * 32 + mt * 16;
            a[mt][0] = __float_as_uint(As[(r + g) * AS_STRIDE + k + t]);
            a[mt][1] = __float_as_uint(As[(r + g + 8) * AS_STRIDE + k + t]);
            a[mt][2] = __float_as_uint(As[(r + g) * AS_STRIDE + k + t + 4]);
            a[mt][3] = __float_as_uint(As[(r + g + 8) * AS_STRIDE + k + t + 4]);
        }
        #pragma unroll
        for (int nt = 0; nt < 8; nt++) {
            int n = nw * 64 + nt * 8;
            uint32_t b0 = __float_as_uint(Bs[(n + g) * BS_STRIDE + k + t]);
            uint32_t b1 = __float_as_uint(Bs[(n + g) * BS_STRIDE + k + t + 4]);
            mma8(d1[0][nt], a[0], b0, b1);
            mma8(d1[1][nt], a[1], b0, b1);
        }
    }
}

// bias + relu + tf32 -> Hs
__device__ __forceinline__ void write_h_bias(float* Hs, const float* bias,
                                             int mw, int nw, int g, int t,
                                             float d1[2][8][4]) {
    #pragma unroll
    for (int mt = 0; mt < 2; mt++) {
        int r = mw * 32 + mt * 16 + g;
        #pragma unroll
        for (int nt = 0; nt < 8; nt++) {
            int c = nw * 64 + nt * 8 + 2 * t;
            float b0 = bias[c], b1v = bias[c + 1];
            Hs[r * HS_STRIDE + c]           = tf32f(fmaxf(d1[mt][nt][0] + b0, 0.f));
            Hs[r * HS_STRIDE + c + 1]       = tf32f(fmaxf(d1[mt][nt][1] + b1v, 0.f));
            Hs[(r + 8) * HS_STRIDE + c]     = tf32f(fmaxf(d1[mt][nt][2] + b0, 0.f));
            Hs[(r + 8) * HS_STRIDE + c + 1] = tf32f(fmaxf(d1[mt][nt][3] + b1v, 0.f));
        }
    }
}

// GEMM2 over a K=128 staged chunk (c = 0 or 1)
__device__ __forceinline__ void gemm2_big(const float* Hs, const float* W2s,
                                          int c, int mw, int nw, int g, int t,
                                          float d2[2][4][4]) {
    #pragma unroll 4
    for (int ks = 0; ks < 16; ks++) {
        int kk = c * 128 + ks * 8;
        int k = ks * 8;
        uint32_t a[2][4];
        #pragma unroll
        for (int mt = 0; mt < 2; mt++) {
            int r = mw * 32 + mt * 16;
            a[mt][0] = __float_as_uint(Hs[(r + g) * HS_STRIDE + kk + t]);
            a[mt][1] = __float_as_uint(Hs[(r + g + 8) * HS_STRIDE + kk + t]);
            a[mt][2] = __float_as_uint(Hs[(r + g) * HS_STRIDE + kk + t + 4]);
            a[mt][3] = __float_as_uint(Hs[(r + g + 8) * HS_STRIDE + kk + t + 4]);
        }
        #pragma unroll
        for (int nt = 0; nt < 4; nt++) {
            int n = nw * 32 + nt * 8;
            uint32_t b0 = __float_as_uint(W2s[(n + g) * W2_STRIDE + k + t]);
            uint32_t b1 = __float_as_uint(W2s[(n + g) * W2_STRIDE + k + t + 4]);
            mma8(d2[0][nt], a[0], b0, b1);
            mma8(d2[1][nt], a[1], b0, b1);
        }
    }
}

// stage one K=128 chunk of W2T [128 x 256] into W2s (stride 132)
__device__ __forceinline__ void stage_w2(float* W2s, const float* __restrict__ W2T,
                                         int c, int tid) {
    int row = tid >> 2, q = tid & 3;
    const float4* sp = (const float4*)(W2T + (size_t)row * 256 + c * 128 + q * 32);
    float4* dp = (float4*)(W2s + row * W2_STRIDE + q * 32);
    #pragma unroll
    for (int j = 0; j < 8; j++) dp[j] = sp[j];
}

// ---------------- edge kernel ------------------------------------------------
__global__ __launch_bounds__(512, 1) void edge_mma_kernel(
    const float* __restrict__ node_in, const float* __restrict__ edge_in,
    const int* __restrict__ src, const int* __restrict__ dst,
    const float* __restrict__ W1T, const float* __restrict__ W2T,
    const float* __restrict__ b2, const float* __restrict__ qb,
    float* __restrict__ edge_out, float* __restrict__ agg) {
    extern __shared__ float sm[];
    float* Hs = sm + HS_OFF;
    float* As = sm + AS_OFF;
    float* Bs = sm + BS_OFF;
    float* W2s = sm + W2_OFF;
    float* qb_s = sm + QB_OFF;
    float* b2_s = sm + B2B_OFF;
    int* ss = (int*)(sm + SS_OFF);
    int* sd = (int*)(sm + SD_OFF);

    const int tid = threadIdx.x;
    const int e0 = blockIdx.x * 128;
    if (tid < 256) qb_s[tid] = qb[tid];
    if (tid < 128) {
        b2_s[tid] = b2[tid];
        ss[tid] = src[e0 + tid];
        sd[tid] = dst[e0 + tid];
    }
    __syncthreads();

    const int w = tid >> 5, lane = tid & 31;
    const int mw = w >> 2, nw = w & 3;
    const int g = lane >> 2, t = lane & 3;
    const int sm_m = tid >> 2, sm_q = tid & 3;
    const int sb_n = tid >> 1, sb_h = tid & 1;
    const int a_src = ss[sm_m], a_dst = sd[sm_m];

    // ---- GEMM1: [128,384] @ [384,256], 12 chunks of K=32 ----
    float d1[2][8][4];
    #pragma unroll
    for (int i = 0; i < 2; i++)
        #pragma unroll
        for (int j = 0; j < 8; j++)
            #pragma unroll
            for (int q = 0; q < 4; q++) d1[i][j][q] = 0.f;

    #pragma unroll 1
    for (int c = 0; c < 12; c++) {
        __syncthreads();
        {   // stage A chunk (gathered, tf32-converted)
            int k = c * 32 + sm_q * 8;
            const float* sp;
            if (k < 128)      sp = node_in + (size_t)a_src * DDIM + k;
            else if (k < 256) sp = node_in + (size_t)a_dst * DDIM + (k - 128);
            else              sp = edge_in + (size_t)(e0 + sm_m) * DDIM + (k - 256);
            float4 v0 = ((const float4*)sp)[0];
            float4 v1 = ((const float4*)sp)[1];
            float* dp = As + sm_m * AS_STRIDE + sm_q * 8;
            dp[0] = tf32f(v0.x); dp[1] = tf32f(v0.y); dp[2] = tf32f(v0.z); dp[3] = tf32f(v0.w);
            dp[4] = tf32f(v1.x); dp[5] = tf32f(v1.y); dp[6] = tf32f(v1.z); dp[7] = tf32f(v1.w);
        }
        {   // stage B chunk (already tf32)
            const float4* sp = (const float4*)(W1T + (size_t)sb_n * 384 + c * 32 + sb_h * 16);
            float4* dp = (float4*)(Bs + sb_n * BS_STRIDE + sb_h * 16);
            dp[0] = sp[0]; dp[1] = sp[1]; dp[2] = sp[2]; dp[3] = sp[3];
        }
        __syncthreads();
        gemm1_chunk_mma(As, Bs, mw, nw, g, t, d1);
    }
    __syncthreads();
    write_h_bias(Hs, qb_s, mw, nw, g, t, d1);
    __syncthreads();

    // ---- GEMM2: [128,256] @ [256,128], 2 chunks of K=128 ----
    float d2[2][4][4];
    #pragma unroll
    for (int i = 0; i < 2; i++)
        #pragma unroll
        for (int j = 0; j < 4; j++)
            #pragma unroll
            for (int q = 0; q < 4; q++) d2[i][j][q] = 0.f;

    #pragma unroll 1
    for (int c = 0; c < 2; c++) {
        stage_w2(W2s, W2T, c, tid);
        __syncthreads();
        gemm2_big(Hs, W2s, c, mw, nw, g, t, d2);
        __syncthreads();
    }

    // ---- epilogue: d2 + bias -> Hs, then coalesced STG + red4 scatter ----
    #pragma unroll
    for (int mt = 0; mt < 2; mt++) {
        #pragma unroll
        for (int half = 0; half < 2; half++) {
            int r = mw * 32 + mt * 16 + g + half * 8;
            #pragma unroll
            for (int nt = 0; nt < 4; nt++) {
                int c = nw * 32 + nt * 8 + 2 * t;
                Hs[r * HS_STRIDE + c]     = d2[mt][nt][half * 2 + 0] + b2_s[c];
                Hs[r * HS_STRIDE + c + 1] = d2[mt][nt][half * 2 + 1] + b2_s[c + 1];
            }
        }
    }
    __syncthreads();
    {
        const int er = tid >> 2, es = tid & 3;
        const int s = ss[er], d = sd[er];
        const float* hrow = Hs + er * HS_STRIDE + es * 32;
        float* eo = edge_out + (size_t)(e0 + er) * DDIM + es * 32;
        float* as_ = agg + (size_t)s * DDIM + es * 32;
        float* ad_ = agg + (size_t)d * DDIM + es * 32;
        #pragma unroll
        for (int jj = 0; jj < 8; jj++) {
            float4 v = ((const float4*)hrow)[jj];
            ((float4*)eo)[jj] = v;
            red4(as_ + 4 * jj, v);
            red4(ad_ + 4 * jj, v);
        }
    }
}

// ---------------- node kernel ------------------------------------------------
__global__ __launch_bounds__(512, 1) void node_mma_kernel(
    const float* __restrict__ node_in, const float* __restrict__ agg,
    const float* __restrict__ W1T, const float* __restrict__ W2T,
    const float* __restrict__ b1, const float* __restrict__ b2,
    float* __restrict__ node_out) {
    extern __shared__ float sm[];
    float* Hs = sm + HS_OFF;
    float* As = sm + AS_OFF;
    float* Bs = sm + BS_OFF;
    float* W2s = sm + W2_OFF;
    float* b1_s = sm + QB_OFF;
    float* b2_s = sm + B2B_OFF;

    const int tid = threadIdx.x;
    const int n0 = blockIdx.x * 128;
    if (tid < 256) b1_s[tid] = b1[tid];
    if (tid < 128) b2_s[tid] = b2[tid];
    __syncthreads();

    const int w = tid >> 5, lane = tid & 31;
    const int mw = w >> 2, nw = w & 3;
    const int g = lane >> 2, t = lane & 3;
    const int sm_m = tid >> 2, sm_q = tid & 3;
    const int sb_n = tid >> 1, sb_h = tid & 1;
    int gm = n0 + sm_m; if (gm >= NN) gm = 0;

    // ---- GEMM1: [128,256] @ [256,256], 8 chunks of K=32 ----
    float d1[2][8][4];
    #pragma unroll
    for (int i = 0; i < 2; i++)
        #pragma unroll
        for (int j = 0; j < 8; j++)
            #pragma unroll
            for (int q = 0; q < 4; q++) d1[i][j][q] = 0.f;

    #pragma unroll 1
    for (int c = 0; c < 8; c++) {
        __syncthreads();
        {
            int k = c * 32 + sm_q * 8;
            const float* sp = (k < 128) ? node_in + (size_t)gm * DDIM + k
                                        : agg + (size_t)gm * DDIM + (k - 128);
            float4 v0 = ((const float4*)sp)[0];
            float4 v1 = ((const float4*)sp)[1];
            float* dp = As + sm_m * AS_STRIDE + sm_q * 8;
            dp[0] = tf32f(v0.x); dp[1] = tf32f(v0.y); dp[2] = tf32f(v0.z); dp[3] = tf32f(v0.w);
            dp[4] = tf32f(v1.x); dp[5] = tf32f(v1.y); dp[6] = tf32f(v1.z); dp[7] = tf32f(v1.w);
        }
        {
            const float4* sp = (const float4*)(W1T + (size_t)sb_n * 256 + c * 32 + sb_h * 16);
            float4* dp = (float4*)(Bs + sb_n * BS_STRIDE + sb_h * 16);
            dp[0] = sp[0]; dp[1] = sp[1]; dp[2] = sp[2]; dp[3] = sp[3];
        }
        __syncthreads();
        gemm1_chunk_mma(As, Bs, mw, nw, g, t, d1);
    }
    __syncthreads();
    write_h_bias(Hs, b1_s, mw, nw, g, t, d1);
    __syncthreads();

    // ---- GEMM2: [128,256] @ [256,128], 2 chunks of K=128 ----
    float d2[2][4][4];
    #pragma unroll
    for (int i = 0; i < 2; i++)
        #pragma unroll
        for (int j = 0; j < 4; j++)
            #pragma unroll
            for (int q = 0; q < 4; q++) d2[i][j][q] = 0.f;

    #pragma unroll 1
    for (int c = 0; c < 2; c++) {
        stage_w2(W2s, W2T, c, tid);
        __syncthreads();
        gemm2_big(Hs, W2s, c, mw, nw, g, t, d2);
        __syncthreads();
    }

    // ---- epilogue: direct stores (guarded) ----
    #pragma unroll
    for (int mt = 0; mt < 2; mt++) {
        #pragma unroll
        for (int half = 0; half < 2; half++) {
            int r = n0 + mw * 32 + mt * 16 + g + half * 8;
            if (r < NN) {
                #pragma unroll
                for (int nt = 0; nt < 4; nt++) {
                    int c = nw * 32 + nt * 8 + 2 * t;
                    float* no = node_out + (size_t)r * DDIM + c;
                    no[0] = d2[mt][nt][half * 2 + 0] + b2_s[c];
                    no[1] = d2[mt][nt][half * 2 + 1] + b2_s[c + 1];
                }
            }
        }
    }
}

// ---------------- launch ----------------------------------------------------
extern "C" void kernel_launch(void* const* d_in, const int* in_sizes, int n_in,
                              void* d_out, int out_size) {
    const float* node_emb = (const float*)d_in[0];
    const float* rel_emb  = (const float*)d_in[1];
    const float* q_emb    = (const float*)d_in[2];
    const int*   eidx     = (const int*)d_in[3];
    // d_in[4] = edge_type, unused (matches reference)
    const float* qW  = (const float*)d_in[5];
    const float* qb  = (const float*)d_in[6];
    const float* eW1 = (const float*)d_in[7];
    const float* eb1 = (const float*)d_in[8];
    const float* eW2 = (const float*)d_in[9];
    const float* eb2 = (const float*)d_in[10];
    const float* nW1 = (const float*)d_in[11];
    const float* nb1 = (const float*)d_in[12];
    const float* nW2 = (const float*)d_in[13];
    const float* nb2 = (const float*)d_in[14];
    const float* esW = (const float*)d_in[15];
    const float* esb = (const float*)d_in[16];
    const float* nsW = (const float*)d_in[17];
    const float* nsb = (const float*)d_in[18];
    const int* src = eidx;
    const int* dst = eidx + EE;

    float *nodeA, *nodeB, *edgeA, *edgeB, *agg, *qv, *qbias;
    float *eW1T, *eW2T, *nW1T, *nW2T;
    cudaGetSymbolAddress((void**)&nodeA, g_nodeA);
    cudaGetSymbolAddress((void**)&nodeB, g_nodeB);
    cudaGetSymbolAddress((void**)&edgeA, g_edgeA);
    cudaGetSymbolAddress((void**)&edgeB, g_edgeB);
    cudaGetSymbolAddress((void**)&agg, g_agg);
    cudaGetSymbolAddress((void**)&qv, g_q);
    cudaGetSymbolAddress((void**)&qbias, g_qbias);
    cudaGetSymbolAddress((void**)&eW1T, g_eW1T);
    cudaGetSymbolAddress((void**)&eW2T, g_eW2T);
    cudaGetSymbolAddress((void**)&nW1T, g_nW1T);
    cudaGetSymbolAddress((void**)&nW2T, g_nW2T);

    cudaFuncSetAttribute(edge_mma_kernel, cudaFuncAttributeMaxDynamicSharedMemorySize, SMEM_BYTES);
    cudaFuncSetAttribute(node_mma_kernel, cudaFuncAttributeMaxDynamicSharedMemorySize, SMEM_BYTES);

    // Launch order (layer 0): q_proj(0) zeroA(1) zeroB(2) qbias(3) transposeAll(4)
    // edge(5) <- ncu -s 5 -c 1 captures the edge kernel
    q_proj_kernel<<<1, 128>>>(q_emb, qW, qb, qv);

    const float* nin = node_emb;
    const float* ein = rel_emb;
    float* nout = nodeA; float* nalt = nodeB;
    float* eout = edgeA; float* ealt = edgeB;
    const int NGRID = (NN + 127) / 128;
    const int nhalf4 = NN * DDIM / 8;   // half the agg buffer in float4s

    for (int l = 0; l < LLAY; l++) {
        zero_kernel<<<(nhalf4 + 255) / 256, 256>>>((float4*)agg, nhalf4);
        zero_kernel<<<(nhalf4 + 255) / 256, 256>>>((float4*)agg + nhalf4, nhalf4);
        qbias_kernel<<<1, 256>>>(qv, eW1 + (size_t)l * 512 * HHID, eb1 + (size_t)l * HHID, qbias);
        transpose_all_kernel<<<896, 256>>>(
            eW1 + (size_t)l * 512 * HHID, eW2 + (size_t)l * HHID * DDIM,
            nW1 + (size_t)l * 2 * DDIM * HHID, nW2 + (size_t)l * HHID * DDIM,
            eW1T, eW2T, nW1T, nW2T);

        edge_mma_kernel<<<EE / 128, 512, SMEM_BYTES>>>(nin, ein, src, dst, eW1T, eW2T,
                                                       eb2 + (size_t)l * DDIM, qbias, eout, agg);
        node_mma_kernel<<<NGRID, 512, SMEM_BYTES>>>(nin, agg, nW1T, nW2T,
                                                    nb1 + (size_t)l * HHID,
                                                    nb2 + (size_t)l * DDIM, nout);
        nin = nout; ein = eout;
        float* tptr;
        tptr = nout; nout = nalt; nalt = tptr;
        tptr = eout; eout = ealt; ealt = tptr;
    }

    float* outp = (float*)d_out;
    score_kernel<<<(NN + 7) / 8, 256>>>(nin, nsW, nsb, outp, NN);
    score_kernel<<<(EE + 7) / 8, 256>>>(ein, esW, esb, outp + NN, EE);
}

// round 12
// speedup vs baseline: 1.1710x; 1.1710x over previous
#include <cuda_runtime.h>
#include <cstdint>
#include <math.h>

#define NN 100000
#define EE 640000
#define DDIM 128
#define HHID 256
#define LLAY 3
#define QDIM 768

// ---------------- device scratch (no allocations allowed) -------------------
__device__ float g_nodeA[(size_t)NN * DDIM];
__device__ float g_nodeB[(size_t)NN * DDIM];
__device__ float g_edgeA[(size_t)EE * DDIM];
__device__ float g_edgeB[(size_t)EE * DDIM];
__device__ float g_agg[(size_t)NN * DDIM];
__device__ float g_qbias[LLAY * HHID];
__device__ float g_eW1T[LLAY * 256 * 384];   // [N=256, K=384] tf32 per layer
__device__ float g_eW2T[LLAY * 128 * 256];   // [N=128, K=256] tf32 per layer
__device__ float g_nW1T[LLAY * 256 * 256];   // [N=256, K=256] tf32 per layer
__device__ float g_nW2T[LLAY * 128 * 256];   // [N=128, K=256] tf32 per layer

// ---------------- helpers ----------------------------------------------------
__device__ __forceinline__ uint32_t f2tf32(float f) {
    uint32_t u;
    asm("cvt.rna.tf32.f32 %0, %1;" : "=r"(u) : "f"(f));
    return u;
}
__device__ __forceinline__ float tf32f(float f) { return __uint_as_float(f2tf32(f)); }

__device__ __forceinline__ void mma8(float* d, const uint32_t* a, uint32_t b0, uint32_t b1) {
    asm volatile(
        "mma.sync.aligned.m16n8k8.row.col.f32.tf32.tf32.f32 "
        "{%0,%1,%2,%3}, {%4,%5,%6,%7}, {%8,%9}, {%0,%1,%2,%3};"
        : "+f"(d[0]), "+f"(d[1]), "+f"(d[2]), "+f"(d[3])
        : "r"(a[0]), "r"(a[1]), "r"(a[2]), "r"(a[3]), "r"(b0), "r"(b1));
}
__device__ __forceinline__ void red4(float* p, float4 v) {
    asm volatile("red.global.add.v4.f32 [%0], {%1, %2, %3, %4};"
                 :: "l"(p), "f"(v.x), "f"(v.y), "f"(v.z), "f"(v.w) : "memory");
}

// smem layout in float words (exact R5 layout — the 6007us configuration)
enum {
    HS_STRIDE = 264,
    HS_OFF = 0,                       // 128 x 264           = 33792
    AS_OFF = 33792, AS_STRIDE = 36,   // 128 x 36            = 4608
    BS_OFF = 38400, BS_STRIDE = 36,   // 256 x 36            = 9216
    QB_OFF = 47616,                   // 256
    B2_OFF = 47872,                   // 128
    SS_OFF = 48000,                   // 128 (int)
    SD_OFF = 48128,                   // 128 (int)
    SM_WORDS = 48256
};
#define SMEM_BYTES (SM_WORDS * 4)

// ---------------- prep kernels -----------------------------------------------
__global__ void zero_kernel(float4* p, int n4) {
    int i = blockIdx.x * blockDim.x + threadIdx.x;
    if (i < n4) p[i] = make_float4(0.f, 0.f, 0.f, 0.f);
}

// One launch: q = qe@qW + qb (per-block redundant), then qbias for each layer.
// grid = LLAY blocks x 256 threads; block l computes g_qbias[l*256 .. +256)
__global__ void qprep_kernel(const float* __restrict__ qe, const float* __restrict__ qW,
                             const float* __restrict__ qb, const float* __restrict__ eW1,
                             const float* __restrict__ eb1, float* __restrict__ qbias) {
    __shared__ float qs[DDIM];
    int tid = threadIdx.x;
    int l = blockIdx.x;
    if (tid < DDIM) {
        float s = qb[tid];
        #pragma unroll 8
        for (int k = 0; k < QDIM; k++) s += qe[k] * qW[(size_t)k * DDIM + tid];
        qs[tid] = s;
    }
    __syncthreads();
    const float* eW1l = eW1 + (size_t)l * 512 * HHID;
    float s = eb1[l * HHID + tid];
    #pragma unroll 8
    for (int k = 0; k < DDIM; k++) s += qs[k] * eW1l[(size_t)(384 + k) * HHID + tid];
    qbias[l * HHID + tid] = s;
}

// One launch: transpose+tf32 all 4 weight mats for all 3 layers.
// grid = LLAY * 896 blocks x 256 threads
__global__ void transpose3_kernel(
    const float* __restrict__ eW1, const float* __restrict__ eW2,
    const float* __restrict__ nW1, const float* __restrict__ nW2,
    float* __restrict__ eW1T, float* __restrict__ eW2T,
    float* __restrict__ nW1T, float* __restrict__ nW2T) {
    int l = blockIdx.x / 896;
    int b = blockIdx.x % 896;
    const float* in; float* out; int K, N, base;
    if (b < 384)      { in = eW1 + (size_t)l * 512 * HHID;     out = eW1T + (size_t)l * 256 * 384; K = 384; N = 256; base = 0; }
    else if (b < 512) { in = eW2 + (size_t)l * HHID * DDIM;    out = eW2T + (size_t)l * 128 * 256; K = 256; N = 128; base = 384; }
    else if (b < 768) { in = nW1 + (size_t)l * 2 * DDIM * HHID; out = nW1T + (size_t)l * 256 * 256; K = 256; N = 256; base = 512; }
    else              { in = nW2 + (size_t)l * HHID * DDIM;    out = nW2T + (size_t)l * 128 * 256; K = 256; N = 128; base = 768; }
    int i = (b - base) * 256 + threadIdx.x;
    int n = i / K, k = i - n * K;
    out[i] = tf32f(in[(size_t)k * N + n]);
}

__global__ void score_kernel(const float* __restrict__ h, const float* __restrict__ w,
                             const float* __restrict__ bptr, float* __restrict__ out, int count) {
    int gwarp = (blockIdx.x * blockDim.x + threadIdx.x) >> 5;
    int lane = threadIdx.x & 31;
    if (gwarp >= count) return;
    float4 a = ((const float4*)(h + (size_t)gwarp * DDIM))[lane];
    float4 wv = ((const float4*)w)[lane];
    float s = a.x * wv.x + a.y * wv.y + a.z * wv.z + a.w * wv.w;
    #pragma unroll
    for (int o = 16; o; o >>= 1) s += __shfl_xor_sync(0xffffffffu, s, o);
    if (lane == 0) out[gwarp] = 1.f / (1.f + expf(-(s + bptr[0])));
}

// ---------------- shared GEMM pieces (exact R5) -------------------------------
__device__ __forceinline__ void gemm1_chunk_mma(const float* As, const float* Bs,
                                                int mw, int nw, int g, int t,
                                                float d1[2][8][4]) {
    #pragma unroll
    for (int ks = 0; ks < 4; ks++) {
        int k = ks * 8;
        uint32_t a[2][4];
        #pragma unroll
        for (int mt = 0; mt < 2; mt++) {
            int r = mw * 32 + mt * 16;
            a[mt][0] = __float_as_uint(As[(r + g) * AS_STRIDE + k + t]);
            a[mt][1] = __float_as_uint(As[(r + g + 8) * AS_STRIDE + k + t]);
            a[mt][2] = __float_as_uint(As[(r + g) * AS_STRIDE + k + t + 4]);
            a[mt][3] = __float_as_uint(As[(r + g + 8) * AS_STRIDE + k + t + 4]);
        }
        #pragma unroll
        for (int nt = 0; nt < 8; nt++) {
            int n = nw * 64 + nt * 8;
            uint32_t b0 = __float_as_uint(Bs[(n + g) * BS_STRIDE + k + t]);
            uint32_t b1 = __float_as_uint(Bs[(n + g) * BS_STRIDE + k + t + 4]);
            mma8(d1[0][nt], a[0], b0, b1);
            mma8(d1[1][nt], a[1], b0, b1);
        }
    }
}

__device__ __forceinline__ void write_h_bias(float* Hs, const float* bias,
                                             int mw, int nw, int g, int t,
                                             float d1[2][8][4]) {
    #pragma unroll
    for (int mt = 0; mt < 2; mt++) {
        int r = mw * 32 + mt * 16 + g;
        #pragma unroll
        for (int nt = 0; nt < 8; nt++) {
            int c = nw * 64 + nt * 8 + 2 * t;
            float b0 = bias[c], b1v = bias[c + 1];
            Hs[r * HS_STRIDE + c]           = tf32f(fmaxf(d1[mt][nt][0] + b0, 0.f));
            Hs[r * HS_STRIDE + c + 1]       = tf32f(fmaxf(d1[mt][nt][1] + b1v, 0.f));
            Hs[(r + 8) * HS_STRIDE + c]     = tf32f(fmaxf(d1[mt][nt][2] + b0, 0.f));
            Hs[(r + 8) * HS_STRIDE + c + 1] = tf32f(fmaxf(d1[mt][nt][3] + b1v, 0.f));
        }
    }
}

__device__ __forceinline__ void gemm2_chunk_mma(const float* Hs, const float* Bs,
                                                int c, int mw, int nw, int g, int t,
                                                float d2[2][4][4]) {
    #pragma unroll
    for (int ks = 0; ks < 4; ks++) {
        int kk = c * 32 + ks * 8;
        int k = ks * 8;
        uint32_t a[2][4];
        #pragma unroll
        for (int mt = 0; mt < 2; mt++) {
            int r = mw * 32 + mt * 16;
            a[mt][0] = __float_as_uint(Hs[(r + g) * HS_STRIDE + kk + t]);
            a[mt][1] = __float_as_uint(Hs[(r + g + 8) * HS_STRIDE + kk + t]);
            a[mt][2] = __float_as_uint(Hs[(r + g) * HS_STRIDE + kk + t + 4]);
            a[mt][3] = __float_as_uint(Hs[(r + g + 8) * HS_STRIDE + kk + t + 4]);
        }
        #pragma unroll
        for (int nt = 0; nt < 4; nt++) {
            int n = nw * 32 + nt * 8;
            uint32_t b0 = __float_as_uint(Bs[(n + g) * BS_STRIDE + k + t]);
            uint32_t b1 = __float_as_uint(Bs[(n + g) * BS_STRIDE + k + t + 4]);
            mma8(d2[0][nt], a[0], b0, b1);
            mma8(d2[1][nt], a[1], b0, b1);
        }
    }
}

// ---------------- edge kernel (exact R5 body) ---------------------------------
__global__ __launch_bounds__(512, 1) void edge_mma_kernel(
    const float* __restrict__ node_in, const float* __restrict__ edge_in,
    const int* __restrict__ src, const int* __restrict__ dst,
    const float* __restrict__ W1T, const float* __restrict__ W2T,
    const float* __restrict__ b2, const float* __restrict__ qb,
    float* __restrict__ edge_out, float* __restrict__ agg) {
    extern __shared__ float sm[];
    float* Hs = sm + HS_OFF;
    float* As = sm + AS_OFF;
    float* Bs = sm + BS_OFF;
    float* qb_s = sm + QB_OFF;
    float* b2_s = sm + B2_OFF;
    int* ss = (int*)(sm + SS_OFF);
    int* sd = (int*)(sm + SD_OFF);

    const int tid = threadIdx.x;
    const int e0 = blockIdx.x * 128;
    if (tid < 256) qb_s[tid] = qb[tid];
    if (tid < 128) {
        b2_s[tid] = b2[tid];
        ss[tid] = src[e0 + tid];
        sd[tid] = dst[e0 + tid];
    }
    __syncthreads();

    const int w = tid >> 5, lane = tid & 31;
    const int mw = w >> 2, nw = w & 3;
    const int g = lane >> 2, t = lane & 3;
    const int sm_m = tid >> 2, sm_q = tid & 3;
    const int sb_n = tid >> 1, sb_h = tid & 1;
    const int s2_n = tid >> 2, s2_q = tid & 3;
    const int a_src = ss[sm_m], a_dst = sd[sm_m];

    // ---- GEMM1: [128,384] @ [384,256], 12 chunks ----
    float d1[2][8][4];
    #pragma unroll
    for (int i = 0; i < 2; i++)
        #pragma unroll
        for (int j = 0; j < 8; j++)
            #pragma unroll
            for (int q = 0; q < 4; q++) d1[i][j][q] = 0.f;

    #pragma unroll 1
    for (int c = 0; c < 12; c++) {
        __syncthreads();
        {
            int k = c * 32 + sm_q * 8;
            const float* sp;
            if (k < 128)      sp = node_in + (size_t)a_src * DDIM + k;
            else if (k < 256) sp = node_in + (size_t)a_dst * DDIM + (k - 128);
            else              sp = edge_in + (size_t)(e0 + sm_m) * DDIM + (k - 256);
            float4 v0 = ((const float4*)sp)[0];
            float4 v1 = ((const float4*)sp)[1];
            float* dp = As + sm_m * AS_STRIDE + sm_q * 8;
            dp[0] = tf32f(v0.x); dp[1] = tf32f(v0.y); dp[2] = tf32f(v0.z); dp[3] = tf32f(v0.w);
            dp[4] = tf32f(v1.x); dp[5] = tf32f(v1.y); dp[6] = tf32f(v1.z); dp[7] = tf32f(v1.w);
        }
        {
            const float4* sp = (const float4*)(W1T + (size_t)sb_n * 384 + c * 32 + sb_h * 16);
            float4* dp = (float4*)(Bs + sb_n * BS_STRIDE + sb_h * 16);
            dp[0] = sp[0]; dp[1] = sp[1]; dp[2] = sp[2]; dp[3] = sp[3];
        }
        __syncthreads();
        gemm1_chunk_mma(As, Bs, mw, nw, g, t, d1);
    }

    write_h_bias(Hs, qb_s, mw, nw, g, t, d1);

    // ---- GEMM2: [128,256] @ [256,128], 8 chunks ----
    float d2[2][4][4];
    #pragma unroll
    for (int i = 0; i < 2; i++)
        #pragma unroll
        for (int j = 0; j < 4; j++)
            #pragma unroll
            for (int q = 0; q < 4; q++) d2[i][j][q] = 0.f;

    #pragma unroll 1
    for (int c = 0; c < 8; c++) {
        __syncthreads();
        {
            const float4* sp = (const float4*)(W2T + (size_t)s2_n * 256 + c * 32 + s2_q * 8);
            float4* dp = (float4*)(Bs + s2_n * BS_STRIDE + s2_q * 8);
            dp[0] = sp[0]; dp[1] = sp[1];
        }
        __syncthreads();
        gemm2_chunk_mma(Hs, Bs, c, mw, nw, g, t, d2);
    }
    __syncthreads();

    // ---- epilogue: d2 + bias -> Hs, then coalesced STG + red4 scatter ----
    #pragma unroll
    for (int mt = 0; mt < 2; mt++) {
        #pragma unroll
        for (int half = 0; half < 2; half++) {
            int r = mw * 32 + mt * 16 + g + half * 8;
            #pragma unroll
            for (int nt = 0; nt < 4; nt++) {
                int c = nw * 32 + nt * 8 + 2 * t;
                Hs[r * HS_STRIDE + c]     = d2[mt][nt][half * 2 + 0] + b2_s[c];
                Hs[r * HS_STRIDE + c + 1] = d2[mt][nt][half * 2 + 1] + b2_s[c + 1];
            }
        }
    }
    __syncthreads();
    {
        const int er = tid >> 2, es = tid & 3;
        const int s = ss[er], d = sd[er];
        const float* hrow = Hs + er * HS_STRIDE + es * 32;
        float* eo = edge_out + (size_t)(e0 + er) * DDIM + es * 32;
        float* as_ = agg + (size_t)s * DDIM + es * 32;
        float* ad_ = agg + (size_t)d * DDIM + es * 32;
        #pragma unroll
        for (int jj = 0; jj < 8; jj++) {
            float4 v = ((const float4*)hrow)[jj];
            ((float4*)eo)[jj] = v;
            red4(as_ + 4 * jj, v);
            red4(ad_ + 4 * jj, v);
        }
    }
}

// ---------------- node kernel (exact R5 body) ---------------------------------
__global__ __launch_bounds__(512, 1) void node_mma_kernel(
    const float* __restrict__ node_in, const float* __restrict__ agg,
    const float* __restrict__ W1T, const float* __restrict__ W2T,
    const float* __restrict__ b1, const float* __restrict__ b2,
    float* __restrict__ node_out) {
    extern __shared__ float sm[];
    float* Hs = sm + HS_OFF;
    float* As = sm + AS_OFF;
    float* Bs = sm + BS_OFF;
    float* b1_s = sm + QB_OFF;
    float* b2_s = sm + B2_OFF;

    const int tid = threadIdx.x;
    const int n0 = blockIdx.x * 128;
    if (tid < 256) b1_s[tid] = b1[tid];
    if (tid < 128) b2_s[tid] = b2[tid];
    __syncthreads();

    const int w = tid >> 5, lane = tid & 31;
    const int mw = w >> 2, nw = w & 3;
    const int g = lane >> 2, t = lane & 3;
    const int sm_m = tid >> 2, sm_q = tid & 3;
    const int sb_n = tid >> 1, sb_h = tid & 1;
    const int s2_n = tid >> 2, s2_q = tid & 3;
    int gm = n0 + sm_m; if (gm >= NN) gm = 0;

    float d1[2][8][4];
    #pragma unroll
    for (int i = 0; i < 2; i++)
        #pragma unroll
        for (int j = 0; j < 8; j++)
            #pragma unroll
            for (int q = 0; q < 4; q++) d1[i][j][q] = 0.f;

    #pragma unroll 1
    for (int c = 0; c < 8; c++) {
        __syncthreads();
        {
            int k = c * 32 + sm_q * 8;
            const float* sp = (k < 128) ? node_in + (size_t)gm * DDIM + k
                                        : agg + (size_t)gm * DDIM + (k - 128);
            float4 v0 = ((const float4*)sp)[0];
            float4 v1 = ((const float4*)sp)[1];
            float* dp = As + sm_m * AS_STRIDE + sm_q * 8;
            dp[0] = tf32f(v0.x); dp[1] = tf32f(v0.y); dp[2] = tf32f(v0.z); dp[3] = tf32f(v0.w);
            dp[4] = tf32f(v1.x); dp[5] = tf32f(v1.y); dp[6] = tf32f(v1.z); dp[7] = tf32f(v1.w);
        }
        {
            const float4* sp = (const float4*)(W1T + (size_t)sb_n * 256 + c * 32 + sb_h * 16);
            float4* dp = (float4*)(Bs + sb_n * BS_STRIDE + sb_h * 16);
            dp[0] = sp[0]; dp[1] = sp[1]; dp[2] = sp[2]; dp[3] = sp[3];
        }
        __syncthreads();
        gemm1_chunk_mma(As, Bs, mw, nw, g, t, d1);
    }

    write_h_bias(Hs, b1_s, mw, nw, g, t, d1);

    float d2[2][4][4];
    #pragma unroll
    for (int i = 0; i < 2; i++)
        #pragma unroll
        for (int j = 0; j < 4; j++)
            #pragma unroll
            for (int q = 0; q < 4; q++) d2[i][j][q] = 0.f;

    #pragma unroll 1
    for (int c = 0; c < 8; c++) {
        __syncthreads();
        {
            const float4* sp = (const float4*)(W2T + (size_t)s2_n * 256 + c * 32 + s2_q * 8);
            float4* dp = (float4*)(Bs + s2_n * BS_STRIDE + s2_q * 8);
            dp[0] = sp[0]; dp[1] = sp[1];
        }
        __syncthreads();
        gemm2_chunk_mma(Hs, Bs, c, mw, nw, g, t, d2);
    }

    #pragma unroll
    for (int mt = 0; mt < 2; mt++) {
        #pragma unroll
        for (int half = 0; half < 2; half++) {
            int r = n0 + mw * 32 + mt * 16 + g + half * 8;
            if (r < NN) {
                #pragma unroll
                for (int nt = 0; nt < 4; nt++) {
                    int c = nw * 32 + nt * 8 + 2 * t;
                    float* no = node_out + (size_t)r * DDIM + c;
                    no[0] = d2[mt][nt][half * 2 + 0] + b2_s[c];
                    no[1] = d2[mt][nt][half * 2 + 1] + b2_s[c + 1];
                }
            }
        }
    }
}

// ---------------- launch ----------------------------------------------------
extern "C" void kernel_launch(void* const* d_in, const int* in_sizes, int n_in,
                              void* d_out, int out_size) {
    const float* node_emb = (const float*)d_in[0];
    const float* rel_emb  = (const float*)d_in[1];
    const float* q_emb    = (const float*)d_in[2];
    const int*   eidx     = (const int*)d_in[3];
    // d_in[4] = edge_type, unused (matches reference)
    const float* qW  = (const float*)d_in[5];
    const float* qb  = (const float*)d_in[6];
    const float* eW1 = (const float*)d_in[7];
    const float* eb1 = (const float*)d_in[8];
    const float* eW2 = (const float*)d_in[9];
    const float* eb2 = (const float*)d_in[10];
    const float* nW1 = (const float*)d_in[11];
    const float* nb1 = (const float*)d_in[12];
    const float* nW2 = (const float*)d_in[13];
    const float* nb2 = (const float*)d_in[14];
    const float* esW = (const float*)d_in[15];
    const float* esb = (const float*)d_in[16];
    const float* nsW = (const float*)d_in[17];
    const float* nsb = (const float*)d_in[18];
    const int* src = eidx;
    const int* dst = eidx + EE;

    float *nodeA, *nodeB, *edgeA, *edgeB, *agg, *qbias;
    float *eW1T, *eW2T, *nW1T, *nW2T;
    cudaGetSymbolAddress((void**)&nodeA, g_nodeA);
    cudaGetSymbolAddress((void**)&nodeB, g_nodeB);
    cudaGetSymbolAddress((void**)&edgeA, g_edgeA);
    cudaGetSymbolAddress((void**)&edgeB, g_edgeB);
    cudaGetSymbolAddress((void**)&agg, g_agg);
    cudaGetSymbolAddress((void**)&qbias, g_qbias);
    cudaGetSymbolAddress((void**)&eW1T, g_eW1T);
    cudaGetSymbolAddress((void**)&eW2T, g_eW2T);
    cudaGetSymbolAddress((void**)&nW1T, g_nW1T);
    cudaGetSymbolAddress((void**)&nW2T, g_nW2T);

    cudaFuncSetAttribute(edge_mma_kernel, cudaFuncAttributeMaxDynamicSharedMemorySize, SMEM_BYTES);
    cudaFuncSetAttribute(node_mma_kernel, cudaFuncAttributeMaxDynamicSharedMemorySize, SMEM_BYTES);

    // User launch order: qprep(0) transpose3(1) zero(2) edge(3) node(4) zero(5) ...
    // With the harness's 2 internal pre-launches, ncu -s 5 -c 1 captures edge(3).
    qprep_kernel<<<LLAY, 256>>>(q_emb, qW, qb, eW1, eb1, qbias);
    transpose3_kernel<<<LLAY * 896, 256>>>(eW1, eW2, nW1, nW2, eW1T, eW2T, nW1T, nW2T);

    const float* nin = node_emb;
    const float* ein = rel_emb;
    float* nout = nodeA; float* nalt = nodeB;
    float* eout = edgeA; float* ealt = edgeB;
    const int NGRID = (NN + 127) / 128;
    const int n4 = NN * DDIM / 4;

    zero_kernel<<<(n4 + 255) / 256, 256>>>((float4*)agg, n4);

    for (int l = 0; l < LLAY; l++) {
        edge_mma_kernel<<<EE / 128, 512, SMEM_BYTES>>>(
            nin, ein, src, dst,
            eW1T + (size_t)l * 256 * 384, eW2T + (size_t)l * 128 * 256,
            eb2 + (size_t)l * DDIM, qbias + (size_t)l * HHID, eout, agg);
        node_mma_kernel<<<NGRID, 512, SMEM_BYTES>>>(
            nin, agg,
            nW1T + (size_t)l * 256 * 256, nW2T + (size_t)l * 128 * 256,
            nb1 + (size_t)l * HHID, nb2 + (size_t)l * DDIM, nout);
        if (l + 1 < LLAY)
            zero_kernel<<<(n4 + 255) / 256, 256>>>((float4*)agg, n4);
        nin = nout; ein = eout;
        float* tptr;
        tptr = nout; nout = nalt; nalt = tptr;
        tptr = eout; eout = ealt; ealt = tptr;
    }

    float* outp = (float*)d_out;
    score_kernel<<<(NN + 7) / 8, 256>>>(nin, nsW, nsb, outp, NN);
    score_kernel<<<(EE + 7) / 8, 256>>>(ein, esW, esb, outp + NN, EE);
}